// round 2
// baseline (speedup 1.0000x reference)
#include <cuda_runtime.h>
#include <math.h>

// Fused FeedForward_denoise kernel.
// B=4, DIM=64, HID=128, H=W=256. Output fp32 [4,64,256,256].
//
// Tile: 16x16 output pixels per block, 256 threads (1 thread = 1 pixel).
// Per channel-pair (cp, cp+64), cp in 0..63:
//   Phase A: compute xc channels {3cp..3cp+2, 192+3cp..194+3cp} on the 20x20
//            halo region (zero outside image — conv zero-padding of xc).
//   B1: grouped 3x3 (w_dw1) for both channels -> gelu gate -> acc[0..31].
//   B2: grouped 3x3 (w_dw3a) on 18x18 region into smem.
//   B3: depthwise 3x3 (w_dw3b) -> gelu gate -> acc[32..63].
// Final: out = acc + b_out.

#define TILE 16

// shared memory offsets (in floats)
#define SM_SX     0          // 64*400  = 25600
#define SM_SPN    25600      // 2*400   = 800
#define SM_XC     26400      // 6*400   = 2400
#define SM_D3A    28800      // 2*324   = 648
#define SM_SWP    29448      // 6*64    = 384
#define SM_WOUT   29832      // 64*64   = 4096
#define SM_WDW1   33928      // 128*27  = 3456
#define SM_WDW3A  37384      // 128*27  = 3456
#define SM_WDW3B  40840      // 128*9   = 1152
#define SM_BDW1   41992      // 128
#define SM_BDW3A  42120      // 128
#define SM_BDW3B  42248      // 128
#define SM_BOUT   42376      // 64
#define SM_WPN    42440      // 128*2   = 256
#define SM_BPN    42696      // 128
#define SM_BIN    42824      // 256
#define SM_TOTAL  43080      // floats -> 172320 bytes

__device__ __forceinline__ float gelu_exact(float v) {
    return 0.5f * v * (1.0f + erff(v * 0.70710678118654752f));
}

__global__ void __launch_bounds__(256, 1)
ffn_fused_kernel(const float* __restrict__ x,
                 const float* __restrict__ pneff,
                 const float* __restrict__ w_in,  const float* __restrict__ b_in,
                 const float* __restrict__ w_pn,  const float* __restrict__ b_pn,
                 const float* __restrict__ w_dw1, const float* __restrict__ b_dw1,
                 const float* __restrict__ w_dw3a,const float* __restrict__ b_dw3a,
                 const float* __restrict__ w_dw3b,const float* __restrict__ b_dw3b,
                 const float* __restrict__ w_out, const float* __restrict__ b_out,
                 float* __restrict__ out)
{
    extern __shared__ float sm[];
    const int tid = threadIdx.x;
    const int bx0 = blockIdx.x * TILE;
    const int by0 = blockIdx.y * TILE;
    const int b   = blockIdx.z;

    // ---- stage weights/biases into shared ----
    for (int v = tid; v < 4096; v += 256) sm[SM_WOUT + v]  = w_out[v];
    for (int v = tid; v < 3456; v += 256) sm[SM_WDW1 + v]  = w_dw1[v];
    for (int v = tid; v < 3456; v += 256) sm[SM_WDW3A + v] = w_dw3a[v];
    for (int v = tid; v < 1152; v += 256) sm[SM_WDW3B + v] = w_dw3b[v];
    if (tid < 128) {
        sm[SM_BDW1  + tid] = b_dw1[tid];
        sm[SM_BDW3A + tid] = b_dw3a[tid];
        sm[SM_BDW3B + tid] = b_dw3b[tid];
        sm[SM_BPN   + tid] = b_pn[tid];
    }
    if (tid < 64) sm[SM_BOUT + tid] = b_out[tid];
    // w_pn (256) and b_in (256): one element per thread
    sm[SM_WPN + tid] = w_pn[tid];
    sm[SM_BIN + tid] = b_in[tid];

    // ---- stage x tile (20x20 halo, 64 channels) and pneff tile ----
    {
        const float* xb = x + (size_t)b * 64 * 65536;
        for (int c = 0; c < 64; ++c) {
            const float* xcp = xb + (size_t)c * 65536;
            for (int p = tid; p < 400; p += 256) {
                int ry = p / 20;
                int rx = p - ry * 20;
                int gy = by0 + ry - 2;
                int gx = bx0 + rx - 2;
                float vv = 0.0f;
                if ((unsigned)gy < 256u && (unsigned)gx < 256u)
                    vv = xcp[gy * 256 + gx];
                sm[SM_SX + c * 400 + p] = vv;
            }
        }
        const float* pnb = pneff + (size_t)b * 2 * 65536;
        for (int c = 0; c < 2; ++c) {
            const float* pcp = pnb + (size_t)c * 65536;
            for (int p = tid; p < 400; p += 256) {
                int ry = p / 20;
                int rx = p - ry * 20;
                int gy = by0 + ry - 2;
                int gx = bx0 + rx - 2;
                float vv = 0.0f;
                if ((unsigned)gy < 256u && (unsigned)gx < 256u)
                    vv = pcp[gy * 256 + gx];
                sm[SM_SPN + c * 400 + p] = vv;
            }
        }
    }

    float acc[64];
#pragma unroll
    for (int o = 0; o < 64; ++o) acc[o] = 0.0f;

    const int ty = tid >> 4;
    const int tx = tid & 15;

    for (int cp = 0; cp < 64; ++cp) {
        const int cA0 = 3 * cp;        // xc channels of group cp
        const int cB0 = 192 + 3 * cp;  // xc channels of group cp+64

        // stage per-pair 1x1 weights (xi channels only; pn uses SM_WPN)
        for (int idx = tid; idx < 384; idx += 256) {
            int j = idx >> 6;
            int k = idx & 63;
            int c = (j < 3) ? (cA0 + j) : (cB0 + (j - 3));
            if (c >= 128)
                sm[SM_SWP + idx] = w_in[(c - 128) * 64 + k];
        }
        __syncthreads();  // sync1: swpair ready; previous-iter readers done

        // ---- Phase A: 6 xc channels on 20x20 halo region ----
        for (int v = tid; v < 600; v += 256) {
            int j  = v / 100;             // 0..5
            int qp = (v - j * 100) * 4;   // base pixel of this quad
            int c  = (j < 3) ? (cA0 + j) : (cB0 + (j - 3));
            float4 r;
            if (c < 128) {
                // pn channel: 2-dot
                float w0 = sm[SM_WPN + 2 * c];
                float w1 = sm[SM_WPN + 2 * c + 1];
                float bb = sm[SM_BPN + c];
                float4 p0 = *(const float4*)(sm + SM_SPN + qp);
                float4 p1 = *(const float4*)(sm + SM_SPN + 400 + qp);
                r.x = fmaf(w0, p0.x, fmaf(w1, p1.x, bb));
                r.y = fmaf(w0, p0.y, fmaf(w1, p1.y, bb));
                r.z = fmaf(w0, p0.z, fmaf(w1, p1.z, bb));
                r.w = fmaf(w0, p0.w, fmaf(w1, p1.w, bb));
            } else {
                // xi channel: 64-dot against x tile
                float bb = sm[SM_BIN + (c - 128)];
                float4 a;
                a.x = bb; a.y = bb; a.z = bb; a.w = bb;
                const float* wr  = sm + SM_SWP + j * 64;
                const float* sxq = sm + SM_SX + qp;
#pragma unroll
                for (int k4 = 0; k4 < 16; ++k4) {
                    float4 w4 = *(const float4*)(wr + 4 * k4);
                    const float* sp = sxq + (4 * k4) * 400;
                    float4 s0 = *(const float4*)(sp);
                    float4 s1 = *(const float4*)(sp + 400);
                    float4 s2 = *(const float4*)(sp + 800);
                    float4 s3 = *(const float4*)(sp + 1200);
                    a.x = fmaf(w4.x, s0.x, a.x); a.y = fmaf(w4.x, s0.y, a.y);
                    a.z = fmaf(w4.x, s0.z, a.z); a.w = fmaf(w4.x, s0.w, a.w);
                    a.x = fmaf(w4.y, s1.x, a.x); a.y = fmaf(w4.y, s1.y, a.y);
                    a.z = fmaf(w4.y, s1.z, a.z); a.w = fmaf(w4.y, s1.w, a.w);
                    a.x = fmaf(w4.z, s2.x, a.x); a.y = fmaf(w4.z, s2.y, a.y);
                    a.z = fmaf(w4.z, s2.z, a.z); a.w = fmaf(w4.z, s2.w, a.w);
                    a.x = fmaf(w4.w, s3.x, a.x); a.y = fmaf(w4.w, s3.y, a.y);
                    a.z = fmaf(w4.w, s3.z, a.z); a.w = fmaf(w4.w, s3.w, a.w);
                }
                r = a;
            }
            // zero-mask out-of-image halo pixels (xc is zero-padded by conv)
#pragma unroll
            for (int e = 0; e < 4; ++e) {
                int p  = qp + e;
                int ry = p / 20;
                int rx = p - ry * 20;
                int gy = by0 + ry - 2;
                int gx = bx0 + rx - 2;
                float val = (e == 0) ? r.x : (e == 1) ? r.y : (e == 2) ? r.z : r.w;
                sm[SM_XC + j * 400 + p] =
                    ((unsigned)gy < 256u && (unsigned)gx < 256u) ? val : 0.0f;
            }
        }
        __syncthreads();  // sync2: xc ready

        // ---- B1: d1 pair, gate, accumulate out channels 0..31 ----
        {
            float d1a = sm[SM_BDW1 + cp];
            float d1b = sm[SM_BDW1 + cp + 64];
            const float* wA = sm + SM_WDW1 + cp * 27;
            const float* wB = sm + SM_WDW1 + (cp + 64) * 27;
#pragma unroll
            for (int j = 0; j < 3; ++j)
#pragma unroll
                for (int ky = 0; ky < 3; ++ky)
#pragma unroll
                    for (int kx = 0; kx < 3; ++kx) {
                        int xi_idx = (ty + 1 + ky) * 20 + (tx + 1 + kx);
                        int wi = j * 9 + ky * 3 + kx;
                        float xa = sm[SM_XC + j * 400 + xi_idx];
                        float xb = sm[SM_XC + (3 + j) * 400 + xi_idx];
                        d1a = fmaf(wA[wi], xa, d1a);
                        d1b = fmaf(wB[wi], xb, d1b);
                    }
            float g1 = gelu_exact(d1a) * d1b;
#pragma unroll
            for (int o = 0; o < 32; ++o)
                acc[o] = fmaf(sm[SM_WOUT + o * 64 + cp], g1, acc[o]);
        }

        // ---- B2: d3a on 18x18 region, both channels ----
        for (int v = tid; v < 648; v += 256) {
            int h = (v >= 324) ? 1 : 0;
            int p = v - h * 324;
            int qy = p / 18;
            int qx = p - qy * 18;
            int gy = by0 + qy - 1;
            int gx = bx0 + qx - 1;
            float r = 0.0f;
            if ((unsigned)gy < 256u && (unsigned)gx < 256u) {
                int ch = cp + h * 64;
                r = sm[SM_BDW3A + ch];
                const float* wd  = sm + SM_WDW3A + ch * 27;
                const float* xc0 = sm + SM_XC + h * 1200;  // 3 channels x 400
#pragma unroll
                for (int j = 0; j < 3; ++j)
#pragma unroll
                    for (int ky = 0; ky < 3; ++ky)
#pragma unroll
                        for (int kx = 0; kx < 3; ++kx)
                            r = fmaf(wd[j * 9 + ky * 3 + kx],
                                     xc0[j * 400 + (qy + ky) * 20 + (qx + kx)], r);
            }
            sm[SM_D3A + h * 324 + p] = r;
        }
        __syncthreads();  // sync3: d3a ready

        // ---- B3: depthwise 3x3 on d3a, gate, accumulate out channels 32..63 ----
        {
            float dA = sm[SM_BDW3B + cp];
            float dB = sm[SM_BDW3B + cp + 64];
            const float* wA = sm + SM_WDW3B + cp * 9;
            const float* wB = sm + SM_WDW3B + (cp + 64) * 9;
#pragma unroll
            for (int ky = 0; ky < 3; ++ky)
#pragma unroll
                for (int kx = 0; kx < 3; ++kx) {
                    int qi = (ty + ky) * 18 + (tx + kx);
                    float a0 = sm[SM_D3A + qi];
                    float a1 = sm[SM_D3A + 324 + qi];
                    dA = fmaf(wA[ky * 3 + kx], a0, dA);
                    dB = fmaf(wB[ky * 3 + kx], a1, dB);
                }
            float g2 = gelu_exact(dA) * dB;
#pragma unroll
            for (int o = 0; o < 32; ++o)
                acc[32 + o] = fmaf(sm[SM_WOUT + (32 + o) * 64 + cp], g2, acc[32 + o]);
        }
        __syncthreads();  // guard d3a/xc reuse in next pair (paired with sync1)
    }

    // ---- write output ----
    {
        float* ob = out + (size_t)b * 64 * 65536
                        + (size_t)(by0 + ty) * 256 + (bx0 + tx);
#pragma unroll
        for (int o = 0; o < 64; ++o)
            ob[(size_t)o * 65536] = acc[o] + sm[SM_BOUT + o];
    }
}

extern "C" void kernel_launch(void* const* d_in, const int* in_sizes, int n_in,
                              void* d_out, int out_size)
{
    (void)in_sizes; (void)n_in; (void)out_size;
    const float* x      = (const float*)d_in[0];
    const float* pneff  = (const float*)d_in[1];
    const float* w_in   = (const float*)d_in[2];
    const float* b_in   = (const float*)d_in[3];
    const float* w_pn   = (const float*)d_in[4];
    const float* b_pn   = (const float*)d_in[5];
    const float* w_dw1  = (const float*)d_in[6];
    const float* b_dw1  = (const float*)d_in[7];
    const float* w_dw3a = (const float*)d_in[8];
    const float* b_dw3a = (const float*)d_in[9];
    const float* w_dw3b = (const float*)d_in[10];
    const float* b_dw3b = (const float*)d_in[11];
    const float* w_out  = (const float*)d_in[12];
    const float* b_out  = (const float*)d_in[13];
    float* out = (float*)d_out;

    const size_t smem_bytes = SM_TOTAL * sizeof(float);
    cudaFuncSetAttribute(ffn_fused_kernel,
                         cudaFuncAttributeMaxDynamicSharedMemorySize,
                         (int)smem_bytes);

    dim3 grid(16, 16, 4);
    dim3 block(256);
    ffn_fused_kernel<<<grid, block, smem_bytes>>>(
        x, pneff, w_in, b_in, w_pn, b_pn, w_dw1, b_dw1,
        w_dw3a, b_dw3a, w_dw3b, b_dw3b, w_out, b_out, out);
}

// round 3
// speedup vs baseline: 1.0483x; 1.0483x over previous
#include <cuda_runtime.h>
#include <math.h>

// Fused FeedForward_denoise kernel.
// B=4, DIM=64, HID=128, H=W=256. Output fp32 [4,64,256,256].
//
// Tile: 16x16 output pixels per block, 256 threads (1 thread = 1 pixel).
// Per channel-pair (cp, cp+64), cp in 0..63:
//   Phase A: compute xc channels {3cp..3cp+2, 192+3cp..194+3cp} on the 20x20
//            halo region (zero outside image — conv zero-padding of xc).
//   B1: grouped 3x3 (w_dw1) for both channels -> gelu gate -> acc[0..31].
//   B2: grouped 3x3 (w_dw3a) on 18x18 region into smem.
//   B3: depthwise 3x3 (w_dw3b) -> gelu gate -> acc[32..63].
// Final: out = acc + b_out.

#define TILE 16

// shared memory offsets (in floats)
#define SM_SX     0          // 64*400  = 25600
#define SM_SPN    25600      // 2*400   = 800
#define SM_XC     26400      // 6*400   = 2400
#define SM_D3A    28800      // 2*324   = 648
#define SM_SWP    29448      // 6*64    = 384
#define SM_WOUT   29832      // 64*64   = 4096
#define SM_WDW1   33928      // 128*27  = 3456
#define SM_WDW3A  37384      // 128*27  = 3456
#define SM_WDW3B  40840      // 128*9   = 1152
#define SM_BDW1   41992      // 128
#define SM_BDW3A  42120      // 128
#define SM_BDW3B  42248      // 128
#define SM_BOUT   42376      // 64
#define SM_WPN    42440      // 128*2   = 256
#define SM_BPN    42696      // 128
#define SM_BIN    42824      // 256
#define SM_TOTAL  43080      // floats -> 172320 bytes

__device__ __forceinline__ float gelu_exact(float v) {
    return 0.5f * v * (1.0f + erff(v * 0.70710678118654752f));
}

__global__ void __launch_bounds__(256, 1)
ffn_fused_kernel(const float* __restrict__ x,
                 const float* __restrict__ pneff,
                 const float* __restrict__ w_in,  const float* __restrict__ b_in,
                 const float* __restrict__ w_pn,  const float* __restrict__ b_pn,
                 const float* __restrict__ w_dw1, const float* __restrict__ b_dw1,
                 const float* __restrict__ w_dw3a,const float* __restrict__ b_dw3a,
                 const float* __restrict__ w_dw3b,const float* __restrict__ b_dw3b,
                 const float* __restrict__ w_out, const float* __restrict__ b_out,
                 float* __restrict__ out)
{
    extern __shared__ float sm[];
    const int tid = threadIdx.x;
    const int bx0 = blockIdx.x * TILE;
    const int by0 = blockIdx.y * TILE;
    const int b   = blockIdx.z;

    // ---- stage weights/biases into shared ----
    for (int v = tid; v < 4096; v += 256) sm[SM_WOUT + v]  = w_out[v];
    for (int v = tid; v < 3456; v += 256) sm[SM_WDW1 + v]  = w_dw1[v];
    for (int v = tid; v < 3456; v += 256) sm[SM_WDW3A + v] = w_dw3a[v];
    for (int v = tid; v < 1152; v += 256) sm[SM_WDW3B + v] = w_dw3b[v];
    if (tid < 128) {
        sm[SM_BDW1  + tid] = b_dw1[tid];
        sm[SM_BDW3A + tid] = b_dw3a[tid];
        sm[SM_BDW3B + tid] = b_dw3b[tid];
        sm[SM_BPN   + tid] = b_pn[tid];
    }
    if (tid < 64) sm[SM_BOUT + tid] = b_out[tid];
    // w_pn (256) and b_in (256): one element per thread
    sm[SM_WPN + tid] = w_pn[tid];
    sm[SM_BIN + tid] = b_in[tid];

    // ---- stage x tile (20x20 halo, 64 channels) and pneff tile ----
    {
        const float* xb = x + (size_t)b * 64 * 65536;
        for (int c = 0; c < 64; ++c) {
            const float* xcp = xb + (size_t)c * 65536;
            for (int p = tid; p < 400; p += 256) {
                int ry = p / 20;
                int rx = p - ry * 20;
                int gy = by0 + ry - 2;
                int gx = bx0 + rx - 2;
                float vv = 0.0f;
                if ((unsigned)gy < 256u && (unsigned)gx < 256u)
                    vv = xcp[gy * 256 + gx];
                sm[SM_SX + c * 400 + p] = vv;
            }
        }
        const float* pnb = pneff + (size_t)b * 2 * 65536;
        for (int c = 0; c < 2; ++c) {
            const float* pcp = pnb + (size_t)c * 65536;
            for (int p = tid; p < 400; p += 256) {
                int ry = p / 20;
                int rx = p - ry * 20;
                int gy = by0 + ry - 2;
                int gx = bx0 + rx - 2;
                float vv = 0.0f;
                if ((unsigned)gy < 256u && (unsigned)gx < 256u)
                    vv = pcp[gy * 256 + gx];
                sm[SM_SPN + c * 400 + p] = vv;
            }
        }
    }

    float acc[64];
#pragma unroll
    for (int o = 0; o < 64; ++o) acc[o] = 0.0f;

    const int ty = tid >> 4;
    const int tx = tid & 15;

    for (int cp = 0; cp < 64; ++cp) {
        const int cA0 = 3 * cp;        // xc channels of group cp
        const int cB0 = 192 + 3 * cp;  // xc channels of group cp+64

        // stage per-pair 1x1 weights (xi channels only; pn uses SM_WPN)
        for (int idx = tid; idx < 384; idx += 256) {
            int j = idx >> 6;
            int k = idx & 63;
            int c = (j < 3) ? (cA0 + j) : (cB0 + (j - 3));
            if (c >= 128)
                sm[SM_SWP + idx] = w_in[(c - 128) * 64 + k];
        }
        __syncthreads();  // sync1: swpair ready; previous-iter readers done

        // ---- Phase A: 6 xc channels on 20x20 halo region ----
        for (int v = tid; v < 600; v += 256) {
            int j  = v / 100;             // 0..5
            int qp = (v - j * 100) * 4;   // base pixel of this quad
            int c  = (j < 3) ? (cA0 + j) : (cB0 + (j - 3));
            float4 r;
            if (c < 128) {
                // pn channel: 2-dot
                float w0 = sm[SM_WPN + 2 * c];
                float w1 = sm[SM_WPN + 2 * c + 1];
                float bb = sm[SM_BPN + c];
                float4 p0 = *(const float4*)(sm + SM_SPN + qp);
                float4 p1 = *(const float4*)(sm + SM_SPN + 400 + qp);
                r.x = fmaf(w0, p0.x, fmaf(w1, p1.x, bb));
                r.y = fmaf(w0, p0.y, fmaf(w1, p1.y, bb));
                r.z = fmaf(w0, p0.z, fmaf(w1, p1.z, bb));
                r.w = fmaf(w0, p0.w, fmaf(w1, p1.w, bb));
            } else {
                // xi channel: 64-dot against x tile
                float bb = sm[SM_BIN + (c - 128)];
                float4 a;
                a.x = bb; a.y = bb; a.z = bb; a.w = bb;
                const float* wr  = sm + SM_SWP + j * 64;
                const float* sxq = sm + SM_SX + qp;
#pragma unroll
                for (int k4 = 0; k4 < 16; ++k4) {
                    float4 w4 = *(const float4*)(wr + 4 * k4);
                    const float* sp = sxq + (4 * k4) * 400;
                    float4 s0 = *(const float4*)(sp);
                    float4 s1 = *(const float4*)(sp + 400);
                    float4 s2 = *(const float4*)(sp + 800);
                    float4 s3 = *(const float4*)(sp + 1200);
                    a.x = fmaf(w4.x, s0.x, a.x); a.y = fmaf(w4.x, s0.y, a.y);
                    a.z = fmaf(w4.x, s0.z, a.z); a.w = fmaf(w4.x, s0.w, a.w);
                    a.x = fmaf(w4.y, s1.x, a.x); a.y = fmaf(w4.y, s1.y, a.y);
                    a.z = fmaf(w4.y, s1.z, a.z); a.w = fmaf(w4.y, s1.w, a.w);
                    a.x = fmaf(w4.z, s2.x, a.x); a.y = fmaf(w4.z, s2.y, a.y);
                    a.z = fmaf(w4.z, s2.z, a.z); a.w = fmaf(w4.z, s2.w, a.w);
                    a.x = fmaf(w4.w, s3.x, a.x); a.y = fmaf(w4.w, s3.y, a.y);
                    a.z = fmaf(w4.w, s3.z, a.z); a.w = fmaf(w4.w, s3.w, a.w);
                }
                r = a;
            }
            // zero-mask out-of-image halo pixels (xc is zero-padded by conv)
#pragma unroll
            for (int e = 0; e < 4; ++e) {
                int p  = qp + e;
                int ry = p / 20;
                int rx = p - ry * 20;
                int gy = by0 + ry - 2;
                int gx = bx0 + rx - 2;
                float val = (e == 0) ? r.x : (e == 1) ? r.y : (e == 2) ? r.z : r.w;
                sm[SM_XC + j * 400 + p] =
                    ((unsigned)gy < 256u && (unsigned)gx < 256u) ? val : 0.0f;
            }
        }
        __syncthreads();  // sync2: xc ready

        // ---- B1: d1 pair, gate, accumulate out channels 0..31 ----
        {
            float d1a = sm[SM_BDW1 + cp];
            float d1b = sm[SM_BDW1 + cp + 64];
            const float* wA = sm + SM_WDW1 + cp * 27;
            const float* wB = sm + SM_WDW1 + (cp + 64) * 27;
#pragma unroll
            for (int j = 0; j < 3; ++j)
#pragma unroll
                for (int ky = 0; ky < 3; ++ky)
#pragma unroll
                    for (int kx = 0; kx < 3; ++kx) {
                        int xi_idx = (ty + 1 + ky) * 20 + (tx + 1 + kx);
                        int wi = j * 9 + ky * 3 + kx;
                        float xa = sm[SM_XC + j * 400 + xi_idx];
                        float xb = sm[SM_XC + (3 + j) * 400 + xi_idx];
                        d1a = fmaf(wA[wi], xa, d1a);
                        d1b = fmaf(wB[wi], xb, d1b);
                    }
            float g1 = gelu_exact(d1a) * d1b;
#pragma unroll
            for (int o = 0; o < 32; ++o)
                acc[o] = fmaf(sm[SM_WOUT + o * 64 + cp], g1, acc[o]);
        }

        // ---- B2: d3a on 18x18 region, both channels ----
        for (int v = tid; v < 648; v += 256) {
            int h = (v >= 324) ? 1 : 0;
            int p = v - h * 324;
            int qy = p / 18;
            int qx = p - qy * 18;
            int gy = by0 + qy - 1;
            int gx = bx0 + qx - 1;
            float r = 0.0f;
            if ((unsigned)gy < 256u && (unsigned)gx < 256u) {
                int ch = cp + h * 64;
                r = sm[SM_BDW3A + ch];
                const float* wd  = sm + SM_WDW3A + ch * 27;
                const float* xc0 = sm + SM_XC + h * 1200;  // 3 channels x 400
#pragma unroll
                for (int j = 0; j < 3; ++j)
#pragma unroll
                    for (int ky = 0; ky < 3; ++ky)
#pragma unroll
                        for (int kx = 0; kx < 3; ++kx)
                            r = fmaf(wd[j * 9 + ky * 3 + kx],
                                     xc0[j * 400 + (qy + ky) * 20 + (qx + kx)], r);
            }
            sm[SM_D3A + h * 324 + p] = r;
        }
        __syncthreads();  // sync3: d3a ready

        // ---- B3: depthwise 3x3 on d3a, gate, accumulate out channels 32..63 ----
        {
            float dA = sm[SM_BDW3B + cp];
            float dB = sm[SM_BDW3B + cp + 64];
            const float* wA = sm + SM_WDW3B + cp * 9;
            const float* wB = sm + SM_WDW3B + (cp + 64) * 9;
#pragma unroll
            for (int ky = 0; ky < 3; ++ky)
#pragma unroll
                for (int kx = 0; kx < 3; ++kx) {
                    int qi = (ty + ky) * 18 + (tx + kx);
                    float a0 = sm[SM_D3A + qi];
                    float a1 = sm[SM_D3A + 324 + qi];
                    dA = fmaf(wA[ky * 3 + kx], a0, dA);
                    dB = fmaf(wB[ky * 3 + kx], a1, dB);
                }
            float g2 = gelu_exact(dA) * dB;
#pragma unroll
            for (int o = 0; o < 32; ++o)
                acc[32 + o] = fmaf(sm[SM_WOUT + (32 + o) * 64 + cp], g2, acc[32 + o]);
        }
        __syncthreads();  // guard d3a/xc reuse in next pair (paired with sync1)
    }

    // ---- write output ----
    {
        float* ob = out + (size_t)b * 64 * 65536
                        + (size_t)(by0 + ty) * 256 + (bx0 + tx);
#pragma unroll
        for (int o = 0; o < 64; ++o)
            ob[(size_t)o * 65536] = acc[o] + sm[SM_BOUT + o];
    }
}

extern "C" void kernel_launch(void* const* d_in, const int* in_sizes, int n_in,
                              void* d_out, int out_size)
{
    (void)in_sizes; (void)n_in; (void)out_size;
    const float* x      = (const float*)d_in[0];
    const float* pneff  = (const float*)d_in[1];
    const float* w_in   = (const float*)d_in[2];
    const float* b_in   = (const float*)d_in[3];
    const float* w_pn   = (const float*)d_in[4];
    const float* b_pn   = (const float*)d_in[5];
    const float* w_dw1  = (const float*)d_in[6];
    const float* b_dw1  = (const float*)d_in[7];
    const float* w_dw3a = (const float*)d_in[8];
    const float* b_dw3a = (const float*)d_in[9];
    const float* w_dw3b = (const float*)d_in[10];
    const float* b_dw3b = (const float*)d_in[11];
    const float* w_out  = (const float*)d_in[12];
    const float* b_out  = (const float*)d_in[13];
    float* out = (float*)d_out;

    const size_t smem_bytes = SM_TOTAL * sizeof(float);
    cudaFuncSetAttribute(ffn_fused_kernel,
                         cudaFuncAttributeMaxDynamicSharedMemorySize,
                         (int)smem_bytes);

    dim3 grid(16, 16, 4);
    dim3 block(256);
    ffn_fused_kernel<<<grid, block, smem_bytes>>>(
        x, pneff, w_in, b_in, w_pn, b_pn, w_dw1, b_dw1,
        w_dw3a, b_dw3a, w_dw3b, b_dw3b, w_out, b_out, out);
}

// round 4
// speedup vs baseline: 1.4230x; 1.3574x over previous
#include <cuda_runtime.h>
#include <math.h>

#define TILE 16
// smem float offsets
#define SM_SX     0        // 64*400
#define SM_SPN    25600    // 2*400
#define SM_XC     26400    // 24*400
#define SM_D3A    36000    // 4*648
#define SM_WT     38592    // 64*24 transposed per-group 1x1 weights
#define SM_WOUTT  40128    // [cp][o] 4096
#define SM_WDW1   44224    // 3456
#define SM_WDW3A  47680    // 3456
#define SM_WDW3B  51136    // 1152
#define SM_BDW1   52288
#define SM_BDW3A  52416
#define SM_BDW3B  52544
#define SM_BOUT   52672
#define SM_WPN    52736    // 256
#define SM_BPN    52992    // 128
#define SM_BIN    53120    // 256
#define SM_TOTAL  53376    // 213504 bytes

__device__ __forceinline__ float gelu_exact(float v) {
    return 0.5f * v * (1.0f + erff(v * 0.70710678118654752f));
}

__global__ void __launch_bounds__(256, 1)
ffn_fused_kernel(const float* __restrict__ x,
                 const float* __restrict__ pneff,
                 const float* __restrict__ w_in,  const float* __restrict__ b_in,
                 const float* __restrict__ w_pn,  const float* __restrict__ b_pn,
                 const float* __restrict__ w_dw1, const float* __restrict__ b_dw1,
                 const float* __restrict__ w_dw3a,const float* __restrict__ b_dw3a,
                 const float* __restrict__ w_dw3b,const float* __restrict__ b_dw3b,
                 const float* __restrict__ w_out, const float* __restrict__ b_out,
                 float* __restrict__ out)
{
    extern __shared__ float sm[];
    const int tid = threadIdx.x;
    const int bx0 = blockIdx.x * TILE;
    const int by0 = blockIdx.y * TILE;
    const int b   = blockIdx.z;

    // ---- stage weights/biases ----
    for (int v = tid; v < 4096; v += 256) {
        int o = v >> 6, cp = v & 63;
        sm[SM_WOUTT + cp * 64 + o] = w_out[v];      // transpose
    }
    for (int v = tid; v < 3456; v += 256) sm[SM_WDW1 + v]  = w_dw1[v];
    for (int v = tid; v < 3456; v += 256) sm[SM_WDW3A + v] = w_dw3a[v];
    for (int v = tid; v < 1152; v += 256) sm[SM_WDW3B + v] = w_dw3b[v];
    if (tid < 128) {
        sm[SM_BDW1  + tid] = b_dw1[tid];
        sm[SM_BDW3A + tid] = b_dw3a[tid];
        sm[SM_BDW3B + tid] = b_dw3b[tid];
        sm[SM_BPN   + tid] = b_pn[tid];
    }
    if (tid < 64) sm[SM_BOUT + tid] = b_out[tid];
    sm[SM_WPN + tid] = w_pn[tid];
    sm[SM_BIN + tid] = b_in[tid];

    // ---- stage x tile (20x20 halo, 64 ch) + pn tile ----
    {
        const float* xb = x + (size_t)b * 64 * 65536;
        for (int c = 0; c < 64; ++c) {
            const float* xcp = xb + (size_t)c * 65536;
            for (int p = tid; p < 400; p += 256) {
                int ry = p / 20, rx = p - ry * 20;
                int gy = by0 + ry - 2, gx = bx0 + rx - 2;
                float vv = 0.0f;
                if ((unsigned)gy < 256u && (unsigned)gx < 256u) vv = xcp[gy * 256 + gx];
                sm[SM_SX + c * 400 + p] = vv;
            }
        }
        const float* pnb = pneff + (size_t)b * 2 * 65536;
        for (int c = 0; c < 2; ++c) {
            const float* pcp = pnb + (size_t)c * 65536;
            for (int p = tid; p < 400; p += 256) {
                int ry = p / 20, rx = p - ry * 20;
                int gy = by0 + ry - 2, gx = bx0 + rx - 2;
                float vv = 0.0f;
                if ((unsigned)gy < 256u && (unsigned)gx < 256u) vv = pcp[gy * 256 + gx];
                sm[SM_SPN + c * 400 + p] = vv;
            }
        }
    }
    __syncthreads();

    // thread owns halo pixels q0 (always) and q1 (tid<144)
    const int q0 = tid;
    const bool has2 = (tid < 144);
    const int q1 = has2 ? (256 + tid) : tid;   // safe address when !has2
    float m0, m1;
    {
        int ry = q0 / 20, rx = q0 - ry * 20;
        m0 = ((unsigned)(by0 + ry - 2) < 256u && (unsigned)(bx0 + rx - 2) < 256u) ? 1.f : 0.f;
        int ry1 = q1 / 20, rx1 = q1 - ry1 * 20;
        m1 = (has2 && (unsigned)(by0 + ry1 - 2) < 256u && (unsigned)(bx0 + rx1 - 2) < 256u) ? 1.f : 0.f;
    }
    const float pnA0 = sm[SM_SPN + q0],       pnB0 = sm[SM_SPN + 400 + q0];
    const float pnA1 = sm[SM_SPN + q1],       pnB1 = sm[SM_SPN + 400 + q1];

    const int ty = tid >> 4;
    const int tx = tid & 15;

    float acc[64];
#pragma unroll
    for (int o = 0; o < 64; ++o) acc[o] = 0.0f;

    for (int g = 0; g < 16; ++g) {
        // ---- stage transposed per-group 1x1 weights: WT[k][slot] ----
        for (int v = tid; v < 1536; v += 256) {
            int k = v / 24, s = v - k * 24;
            int c = (s < 12) ? (12 * g + s) : (180 + 12 * g + s);   // s>=12: 192+12g+(s-12)
            if (c >= 128) sm[SM_WT + v] = w_in[(c - 128) * 64 + k];
        }
        __syncthreads();

        // ---- Phase A: two 12-channel chunks, pixel-owned ----
#pragma unroll
        for (int half = 0; half < 2; ++half) {
            const int cbase = (half == 0) ? (12 * g) : (192 + 12 * g);
            const bool anyXi = (half == 1) || (g >= 10);
            float a0[12], a1[12];
            if (anyXi) {
#pragma unroll
                for (int s = 0; s < 12; ++s) {
                    int xi = cbase + s - 128; xi = xi < 0 ? 0 : xi;
                    float bb = sm[SM_BIN + xi];
                    a0[s] = bb; a1[s] = bb;
                }
                const float* wt = sm + SM_WT + half * 12;
#pragma unroll 4
                for (int k = 0; k < 64; ++k) {
                    float s0 = sm[SM_SX + k * 400 + q0];
                    float s1 = sm[SM_SX + k * 400 + q1];
                    float4 w0 = *(const float4*)(wt + k * 24);
                    float4 w1 = *(const float4*)(wt + k * 24 + 4);
                    float4 w2 = *(const float4*)(wt + k * 24 + 8);
                    a0[0] = fmaf(w0.x, s0, a0[0]);  a1[0] = fmaf(w0.x, s1, a1[0]);
                    a0[1] = fmaf(w0.y, s0, a0[1]);  a1[1] = fmaf(w0.y, s1, a1[1]);
                    a0[2] = fmaf(w0.z, s0, a0[2]);  a1[2] = fmaf(w0.z, s1, a1[2]);
                    a0[3] = fmaf(w0.w, s0, a0[3]);  a1[3] = fmaf(w0.w, s1, a1[3]);
                    a0[4] = fmaf(w1.x, s0, a0[4]);  a1[4] = fmaf(w1.x, s1, a1[4]);
                    a0[5] = fmaf(w1.y, s0, a0[5]);  a1[5] = fmaf(w1.y, s1, a1[5]);
                    a0[6] = fmaf(w1.z, s0, a0[6]);  a1[6] = fmaf(w1.z, s1, a1[6]);
                    a0[7] = fmaf(w1.w, s0, a0[7]);  a1[7] = fmaf(w1.w, s1, a1[7]);
                    a0[8] = fmaf(w2.x, s0, a0[8]);  a1[8] = fmaf(w2.x, s1, a1[8]);
                    a0[9] = fmaf(w2.y, s0, a0[9]);  a1[9] = fmaf(w2.y, s1, a1[9]);
                    a0[10] = fmaf(w2.z, s0, a0[10]); a1[10] = fmaf(w2.z, s1, a1[10]);
                    a0[11] = fmaf(w2.w, s0, a0[11]); a1[11] = fmaf(w2.w, s1, a1[11]);
                }
            }
            // overwrite pn slots (half==0, c<128)
            if (half == 0) {
#pragma unroll
                for (int s = 0; s < 12; ++s) {
                    int c = 12 * g + s;
                    if (c < 128) {
                        float w0 = sm[SM_WPN + 2 * c], w1 = sm[SM_WPN + 2 * c + 1];
                        float bb = sm[SM_BPN + c];
                        a0[s] = fmaf(w0, pnA0, fmaf(w1, pnB0, bb));
                        a1[s] = fmaf(w0, pnA1, fmaf(w1, pnB1, bb));
                    }
                }
            }
#pragma unroll
            for (int s = 0; s < 12; ++s) {
                sm[SM_XC + (half * 12 + s) * 400 + q0] = a0[s] * m0;
                if (has2) sm[SM_XC + (half * 12 + s) * 400 + q1] = a1[s] * m1;
            }
        }
        __syncthreads();   // XC ready

        // ---- B1 + projection (o 0..31) for 4 cps ----
#pragma unroll
        for (int cpl = 0; cpl < 4; ++cpl) {
            const int cp = 4 * g + cpl;
            float d1a = sm[SM_BDW1 + cp];
            float d1b = sm[SM_BDW1 + cp + 64];
            const float* wA = sm + SM_WDW1 + cp * 27;
            const float* wB = sm + SM_WDW1 + (cp + 64) * 27;
            const float* xcA = sm + SM_XC + (3 * cpl) * 400;
            const float* xcB = sm + SM_XC + (12 + 3 * cpl) * 400;
#pragma unroll
            for (int j = 0; j < 3; ++j)
#pragma unroll
                for (int ky = 0; ky < 3; ++ky)
#pragma unroll
                    for (int kx = 0; kx < 3; ++kx) {
                        int xi = (ty + 1 + ky) * 20 + (tx + 1 + kx);
                        int wi = j * 9 + ky * 3 + kx;
                        d1a = fmaf(wA[wi], xcA[j * 400 + xi], d1a);
                        d1b = fmaf(wB[wi], xcB[j * 400 + xi], d1b);
                    }
            float g1 = gelu_exact(d1a) * d1b;
            const float4* wo = (const float4*)(sm + SM_WOUTT + cp * 64);
#pragma unroll
            for (int o4 = 0; o4 < 8; ++o4) {
                float4 w = wo[o4];
                acc[4 * o4]     = fmaf(w.x, g1, acc[4 * o4]);
                acc[4 * o4 + 1] = fmaf(w.y, g1, acc[4 * o4 + 1]);
                acc[4 * o4 + 2] = fmaf(w.z, g1, acc[4 * o4 + 2]);
                acc[4 * o4 + 3] = fmaf(w.w, g1, acc[4 * o4 + 3]);
            }
        }

        // ---- B2: d3a (18x18, 2 ch) for 4 cps ----
        for (int v = tid; v < 2592; v += 256) {
            int cpl = v / 648, rem = v - cpl * 648;
            int h = rem / 324, p = rem - h * 324;
            int qy = p / 18, qx = p - qy * 18;
            int gy = by0 + qy - 1, gx = bx0 + qx - 1;
            float r = 0.0f;
            if ((unsigned)gy < 256u && (unsigned)gx < 256u) {
                int ch = 4 * g + cpl + h * 64;
                r = sm[SM_BDW3A + ch];
                const float* wd  = sm + SM_WDW3A + ch * 27;
                const float* xc0 = sm + SM_XC + (h * 12 + 3 * cpl) * 400;
#pragma unroll
                for (int j = 0; j < 3; ++j)
#pragma unroll
                    for (int ky = 0; ky < 3; ++ky)
#pragma unroll
                        for (int kx = 0; kx < 3; ++kx)
                            r = fmaf(wd[j * 9 + ky * 3 + kx],
                                     xc0[j * 400 + (qy + ky) * 20 + (qx + kx)], r);
            }
            sm[SM_D3A + cpl * 648 + h * 324 + p] = r;
        }
        __syncthreads();   // D3A ready

        // ---- B3 + projection (o 32..63) for 4 cps ----
#pragma unroll
        for (int cpl = 0; cpl < 4; ++cpl) {
            const int cp = 4 * g + cpl;
            float dA = sm[SM_BDW3B + cp];
            float dB = sm[SM_BDW3B + cp + 64];
            const float* wA = sm + SM_WDW3B + cp * 9;
            const float* wB = sm + SM_WDW3B + (cp + 64) * 9;
            const float* dz = sm + SM_D3A + cpl * 648;
#pragma unroll
            for (int ky = 0; ky < 3; ++ky)
#pragma unroll
                for (int kx = 0; kx < 3; ++kx) {
                    int qi = (ty + ky) * 18 + (tx + kx);
                    dA = fmaf(wA[ky * 3 + kx], dz[qi], dA);
                    dB = fmaf(wB[ky * 3 + kx], dz[324 + qi], dB);
                }
            float g2 = gelu_exact(dA) * dB;
            const float4* wo = (const float4*)(sm + SM_WOUTT + cp * 64 + 32);
#pragma unroll
            for (int o4 = 0; o4 < 8; ++o4) {
                float4 w = wo[o4];
                acc[32 + 4 * o4]     = fmaf(w.x, g2, acc[32 + 4 * o4]);
                acc[33 + 4 * o4]     = fmaf(w.y, g2, acc[33 + 4 * o4]);
                acc[34 + 4 * o4]     = fmaf(w.z, g2, acc[34 + 4 * o4]);
                acc[35 + 4 * o4]     = fmaf(w.w, g2, acc[35 + 4 * o4]);
            }
        }
        __syncthreads();   // protect WT/XC/D3A for next group
    }

    // ---- write output ----
    float* ob = out + (size_t)b * 64 * 65536 + (size_t)(by0 + ty) * 256 + (bx0 + tx);
#pragma unroll
    for (int o = 0; o < 64; ++o)
        ob[(size_t)o * 65536] = acc[o] + sm[SM_BOUT + o];
}

extern "C" void kernel_launch(void* const* d_in, const int* in_sizes, int n_in,
                              void* d_out, int out_size)
{
    (void)in_sizes; (void)n_in; (void)out_size;
    const float* x      = (const float*)d_in[0];
    const float* pneff  = (const float*)d_in[1];
    const float* w_in   = (const float*)d_in[2];
    const float* b_in   = (const float*)d_in[3];
    const float* w_pn   = (const float*)d_in[4];
    const float* b_pn   = (const float*)d_in[5];
    const float* w_dw1  = (const float*)d_in[6];
    const float* b_dw1  = (const float*)d_in[7];
    const float* w_dw3a = (const float*)d_in[8];
    const float* b_dw3a = (const float*)d_in[9];
    const float* w_dw3b = (const float*)d_in[10];
    const float* b_dw3b = (const float*)d_in[11];
    const float* w_out  = (const float*)d_in[12];
    const float* b_out  = (const float*)d_in[13];
    float* out = (float*)d_out;

    const size_t smem_bytes = SM_TOTAL * sizeof(float);
    cudaFuncSetAttribute(ffn_fused_kernel,
                         cudaFuncAttributeMaxDynamicSharedMemorySize,
                         (int)smem_bytes);
    dim3 grid(16, 16, 4);
    ffn_fused_kernel<<<grid, 256, smem_bytes>>>(
        x, pneff, w_in, b_in, w_pn, b_pn, w_dw1, b_dw1,
        w_dw3a, b_dw3a, w_dw3b, b_dw3b, w_out, b_out, out);
}

// round 5
// speedup vs baseline: 1.5728x; 1.1053x over previous
#include <cuda_runtime.h>
#include <math.h>
#include <stddef.h>

#define TILE 16
// smem float offsets
#define SM_SX     0        // 64*400 = 25600
#define SM_SPN    25600    // 2*400  = 800
#define SM_XC     26400    // 24*400 = 9600
#define SM_D3A    36000    // 4*648  = 2592
#define SM_WT     38592    // 64*24  = 1536
#define SM_TOTAL  40128    // 160512 bytes

struct CW {
    float wdw1[128 * 27];
    float wdw3a[128 * 27];
    float wdw3b[128 * 9];
    float woutT[64 * 64];   // [cp][o]
    float bdw1[128];
    float bdw3a[128];
    float bdw3b[128];
    float bout[64];
    float wpn[256];
    float bpn[128];
    float bin[256];
};
__constant__ CW cw;
__device__ float g_woutT[64 * 64];

__global__ void prep_woutT(const float* __restrict__ w_out) {
    int i = blockIdx.x * 256 + threadIdx.x;   // 0..4095
    int o = i >> 6, cp = i & 63;
    g_woutT[cp * 64 + o] = w_out[i];
}

__device__ __forceinline__ float gelu_exact(float v) {
    return 0.5f * v * (1.0f + erff(v * 0.70710678118654752f));
}

__global__ void __launch_bounds__(256, 1)
ffn_fused_kernel(const float* __restrict__ x,
                 const float* __restrict__ pneff,
                 const float* __restrict__ w_in,
                 float* __restrict__ out)
{
    extern __shared__ float sm[];
    const int tid = threadIdx.x;
    const int bx0 = blockIdx.x * TILE;
    const int by0 = blockIdx.y * TILE;
    const int b   = blockIdx.z;

    // ---- stage x tile (20x20 halo, 64 ch) + pn tile ----
    {
        const float* xb = x + (size_t)b * 64 * 65536;
        for (int c = 0; c < 64; ++c) {
            const float* xcp = xb + (size_t)c * 65536;
            for (int p = tid; p < 400; p += 256) {
                int ry = p / 20, rx = p - ry * 20;
                int gy = by0 + ry - 2, gx = bx0 + rx - 2;
                float vv = 0.0f;
                if ((unsigned)gy < 256u && (unsigned)gx < 256u) vv = xcp[gy * 256 + gx];
                sm[SM_SX + c * 400 + p] = vv;
            }
        }
        const float* pnb = pneff + (size_t)b * 2 * 65536;
        for (int c = 0; c < 2; ++c) {
            const float* pcp = pnb + (size_t)c * 65536;
            for (int p = tid; p < 400; p += 256) {
                int ry = p / 20, rx = p - ry * 20;
                int gy = by0 + ry - 2, gx = bx0 + rx - 2;
                float vv = 0.0f;
                if ((unsigned)gy < 256u && (unsigned)gx < 256u) vv = pcp[gy * 256 + gx];
                sm[SM_SPN + c * 400 + p] = vv;
            }
        }
    }
    __syncthreads();

    const int q0 = tid;
    const bool has2 = (tid < 144);
    const int q1 = has2 ? (256 + tid) : tid;
    float m0, m1;
    {
        int ry = q0 / 20, rx = q0 - ry * 20;
        m0 = ((unsigned)(by0 + ry - 2) < 256u && (unsigned)(bx0 + rx - 2) < 256u) ? 1.f : 0.f;
        int ry1 = q1 / 20, rx1 = q1 - ry1 * 20;
        m1 = (has2 && (unsigned)(by0 + ry1 - 2) < 256u && (unsigned)(bx0 + rx1 - 2) < 256u) ? 1.f : 0.f;
    }
    const float pnA0 = sm[SM_SPN + q0], pnB0 = sm[SM_SPN + 400 + q0];
    const float pnA1 = sm[SM_SPN + q1], pnB1 = sm[SM_SPN + 400 + q1];

    const int ty = tid >> 4;
    const int tx = tid & 15;
    const int warp = tid >> 5;
    const int lane = tid & 31;

    float acc[64];
#pragma unroll
    for (int o = 0; o < 64; ++o) acc[o] = 0.0f;

    for (int g = 0; g < 16; ++g) {
        // ---- stage transposed per-group 1x1 weights: WT[k][slot] ----
        for (int v = tid; v < 1536; v += 256) {
            int k = v / 24, s = v - k * 24;
            int c = (s < 12) ? (12 * g + s) : (180 + 12 * g + s);
            if (c >= 128) sm[SM_WT + v] = w_in[(c - 128) * 64 + k];
        }
        __syncthreads();

        // ---- Phase A: 24 xc channels, pixel-owned ----
#pragma unroll
        for (int half = 0; half < 2; ++half) {
            const int cbase = (half == 0) ? (12 * g) : (192 + 12 * g);
            const bool anyXi = (half == 1) || (g >= 10);
            float a0[12], a1[12];
            if (anyXi) {
#pragma unroll
                for (int s = 0; s < 12; ++s) {
                    int xi = cbase + s - 128; xi = xi < 0 ? 0 : xi;
                    float bb = cw.bin[xi];
                    a0[s] = bb; a1[s] = bb;
                }
                const float* wt = sm + SM_WT + half * 12;
#pragma unroll 4
                for (int k = 0; k < 64; ++k) {
                    float s0 = sm[SM_SX + k * 400 + q0];
                    float s1 = sm[SM_SX + k * 400 + q1];
                    float4 w0 = *(const float4*)(wt + k * 24);
                    float4 w1 = *(const float4*)(wt + k * 24 + 4);
                    float4 w2 = *(const float4*)(wt + k * 24 + 8);
                    a0[0] = fmaf(w0.x, s0, a0[0]);  a1[0] = fmaf(w0.x, s1, a1[0]);
                    a0[1] = fmaf(w0.y, s0, a0[1]);  a1[1] = fmaf(w0.y, s1, a1[1]);
                    a0[2] = fmaf(w0.z, s0, a0[2]);  a1[2] = fmaf(w0.z, s1, a1[2]);
                    a0[3] = fmaf(w0.w, s0, a0[3]);  a1[3] = fmaf(w0.w, s1, a1[3]);
                    a0[4] = fmaf(w1.x, s0, a0[4]);  a1[4] = fmaf(w1.x, s1, a1[4]);
                    a0[5] = fmaf(w1.y, s0, a0[5]);  a1[5] = fmaf(w1.y, s1, a1[5]);
                    a0[6] = fmaf(w1.z, s0, a0[6]);  a1[6] = fmaf(w1.z, s1, a1[6]);
                    a0[7] = fmaf(w1.w, s0, a0[7]);  a1[7] = fmaf(w1.w, s1, a1[7]);
                    a0[8] = fmaf(w2.x, s0, a0[8]);  a1[8] = fmaf(w2.x, s1, a1[8]);
                    a0[9] = fmaf(w2.y, s0, a0[9]);  a1[9] = fmaf(w2.y, s1, a1[9]);
                    a0[10] = fmaf(w2.z, s0, a0[10]); a1[10] = fmaf(w2.z, s1, a1[10]);
                    a0[11] = fmaf(w2.w, s0, a0[11]); a1[11] = fmaf(w2.w, s1, a1[11]);
                }
            }
            if (half == 0) {
#pragma unroll
                for (int s = 0; s < 12; ++s) {
                    int c = 12 * g + s;
                    if (c < 128) {
                        float w0 = cw.wpn[2 * c], w1 = cw.wpn[2 * c + 1];
                        float bb = cw.bpn[c];
                        a0[s] = fmaf(w0, pnA0, fmaf(w1, pnB0, bb));
                        a1[s] = fmaf(w0, pnA1, fmaf(w1, pnB1, bb));
                    }
                }
            }
#pragma unroll
            for (int s = 0; s < 12; ++s) {
                sm[SM_XC + (half * 12 + s) * 400 + q0] = a0[s] * m0;
                if (has2) sm[SM_XC + (half * 12 + s) * 400 + q1] = a1[s] * m1;
            }
        }
        __syncthreads();   // XC ready

        // ---- B1 + projection (o 0..31), pixel-owned, weights via LDCU ----
#pragma unroll
        for (int cpl = 0; cpl < 4; ++cpl) {
            const int cp = 4 * g + cpl;
            float d1a = cw.bdw1[cp];
            float d1b = cw.bdw1[cp + 64];
            const float* xcA = sm + SM_XC + (3 * cpl) * 400;
            const float* xcB = sm + SM_XC + (12 + 3 * cpl) * 400;
#pragma unroll
            for (int j = 0; j < 3; ++j)
#pragma unroll
                for (int ky = 0; ky < 3; ++ky)
#pragma unroll
                    for (int kx = 0; kx < 3; ++kx) {
                        int xi = (ty + 1 + ky) * 20 + (tx + 1 + kx);
                        int wi = j * 9 + ky * 3 + kx;
                        d1a = fmaf(cw.wdw1[cp * 27 + wi],        xcA[j * 400 + xi], d1a);
                        d1b = fmaf(cw.wdw1[(cp + 64) * 27 + wi], xcB[j * 400 + xi], d1b);
                    }
            float g1 = gelu_exact(d1a) * d1b;
            const float4* wo = (const float4*)(cw.woutT + cp * 64);
#pragma unroll
            for (int o4 = 0; o4 < 8; ++o4) {
                float4 w = wo[o4];
                acc[4 * o4]     = fmaf(w.x, g1, acc[4 * o4]);
                acc[4 * o4 + 1] = fmaf(w.y, g1, acc[4 * o4 + 1]);
                acc[4 * o4 + 2] = fmaf(w.z, g1, acc[4 * o4 + 2]);
                acc[4 * o4 + 3] = fmaf(w.w, g1, acc[4 * o4 + 3]);
            }
        }

        // ---- B2: warp-specialized d3a, sliding window, weights in regs ----
        {
            const int cpl = warp & 3;
            const int h   = warp >> 2;
            const int ch  = 4 * g + cpl + h * 64;
            float wr[27];
#pragma unroll
            for (int t = 0; t < 27; ++t) wr[t] = cw.wdw3a[ch * 27 + t];
            float bias = cw.bdw3a[ch];
            if (lane < 18) {
                const int r = lane;                 // output row 0..17
                const int gy = by0 + r - 1;
                const bool rowOK = ((unsigned)gy < 256u);
                const float* xc0 = sm + SM_XC + (h * 12 + 3 * cpl) * 400;
                float* d3row = sm + SM_D3A + cpl * 648 + h * 324 + r * 18;
                float c0[9], c1[9], c2[9];
#pragma unroll
                for (int t = 0; t < 9; ++t) {
                    int j = t / 3, ky = t - 3 * j;
                    c0[t] = xc0[j * 400 + (r + ky) * 20 + 0];
                    c1[t] = xc0[j * 400 + (r + ky) * 20 + 1];
                }
#pragma unroll
                for (int qx = 0; qx < 18; ++qx) {
#pragma unroll
                    for (int t = 0; t < 9; ++t) {
                        int j = t / 3, ky = t - 3 * j;
                        c2[t] = xc0[j * 400 + (r + ky) * 20 + qx + 2];
                    }
                    float d = bias;
#pragma unroll
                    for (int t = 0; t < 9; ++t) {
                        int j = t / 3, ky = t - 3 * j;
                        d = fmaf(wr[j * 9 + ky * 3 + 0], c0[t], d);
                        d = fmaf(wr[j * 9 + ky * 3 + 1], c1[t], d);
                        d = fmaf(wr[j * 9 + ky * 3 + 2], c2[t], d);
                    }
                    int gx = bx0 + qx - 1;
                    d3row[qx] = (rowOK && (unsigned)gx < 256u) ? d : 0.0f;
#pragma unroll
                    for (int t = 0; t < 9; ++t) { c0[t] = c1[t]; c1[t] = c2[t]; }
                }
            }
        }
        __syncthreads();   // D3A ready

        // ---- B3 + projection (o 32..63), pixel-owned ----
#pragma unroll
        for (int cpl = 0; cpl < 4; ++cpl) {
            const int cp = 4 * g + cpl;
            float dA = cw.bdw3b[cp];
            float dB = cw.bdw3b[cp + 64];
            const float* dz = sm + SM_D3A + cpl * 648;
#pragma unroll
            for (int ky = 0; ky < 3; ++ky)
#pragma unroll
                for (int kx = 0; kx < 3; ++kx) {
                    int qi = (ty + ky) * 18 + (tx + kx);
                    int wi = ky * 3 + kx;
                    dA = fmaf(cw.wdw3b[cp * 9 + wi],        dz[qi],       dA);
                    dB = fmaf(cw.wdw3b[(cp + 64) * 9 + wi], dz[324 + qi], dB);
                }
            float g2 = gelu_exact(dA) * dB;
            const float4* wo = (const float4*)(cw.woutT + cp * 64 + 32);
#pragma unroll
            for (int o4 = 0; o4 < 8; ++o4) {
                float4 w = wo[o4];
                acc[32 + 4 * o4] = fmaf(w.x, g2, acc[32 + 4 * o4]);
                acc[33 + 4 * o4] = fmaf(w.y, g2, acc[33 + 4 * o4]);
                acc[34 + 4 * o4] = fmaf(w.z, g2, acc[34 + 4 * o4]);
                acc[35 + 4 * o4] = fmaf(w.w, g2, acc[35 + 4 * o4]);
            }
        }
        __syncthreads();   // protect WT/XC/D3A for next group
    }

    float* ob = out + (size_t)b * 64 * 65536 + (size_t)(by0 + ty) * 256 + (bx0 + tx);
#pragma unroll
    for (int o = 0; o < 64; ++o)
        ob[(size_t)o * 65536] = acc[o] + cw.bout[o];
}

extern "C" void kernel_launch(void* const* d_in, const int* in_sizes, int n_in,
                              void* d_out, int out_size)
{
    (void)in_sizes; (void)n_in; (void)out_size;
    const float* x      = (const float*)d_in[0];
    const float* pneff  = (const float*)d_in[1];
    const float* w_in   = (const float*)d_in[2];
    float* out = (float*)d_out;

    // transpose w_out on device, then fill constant bank (all async, stream 0)
    prep_woutT<<<16, 256>>>((const float*)d_in[12]);
    void* p_woutT = nullptr;
    cudaGetSymbolAddress(&p_woutT, g_woutT);

    cudaMemcpyToSymbolAsync(cw, d_in[6],  sizeof(float) * 128 * 27, offsetof(CW, wdw1),  cudaMemcpyDeviceToDevice, 0);
    cudaMemcpyToSymbolAsync(cw, d_in[8],  sizeof(float) * 128 * 27, offsetof(CW, wdw3a), cudaMemcpyDeviceToDevice, 0);
    cudaMemcpyToSymbolAsync(cw, d_in[10], sizeof(float) * 128 * 9,  offsetof(CW, wdw3b), cudaMemcpyDeviceToDevice, 0);
    cudaMemcpyToSymbolAsync(cw, p_woutT,  sizeof(float) * 64 * 64,  offsetof(CW, woutT), cudaMemcpyDeviceToDevice, 0);
    cudaMemcpyToSymbolAsync(cw, d_in[7],  sizeof(float) * 128,      offsetof(CW, bdw1),  cudaMemcpyDeviceToDevice, 0);
    cudaMemcpyToSymbolAsync(cw, d_in[9],  sizeof(float) * 128,      offsetof(CW, bdw3a), cudaMemcpyDeviceToDevice, 0);
    cudaMemcpyToSymbolAsync(cw, d_in[11], sizeof(float) * 128,      offsetof(CW, bdw3b), cudaMemcpyDeviceToDevice, 0);
    cudaMemcpyToSymbolAsync(cw, d_in[13], sizeof(float) * 64,       offsetof(CW, bout),  cudaMemcpyDeviceToDevice, 0);
    cudaMemcpyToSymbolAsync(cw, d_in[4],  sizeof(float) * 256,      offsetof(CW, wpn),   cudaMemcpyDeviceToDevice, 0);
    cudaMemcpyToSymbolAsync(cw, d_in[5],  sizeof(float) * 128,      offsetof(CW, bpn),   cudaMemcpyDeviceToDevice, 0);
    cudaMemcpyToSymbolAsync(cw, d_in[3],  sizeof(float) * 256,      offsetof(CW, bin),   cudaMemcpyDeviceToDevice, 0);

    const size_t smem_bytes = SM_TOTAL * sizeof(float);
    cudaFuncSetAttribute(ffn_fused_kernel,
                         cudaFuncAttributeMaxDynamicSharedMemorySize,
                         (int)smem_bytes);
    dim3 grid(16, 16, 4);
    ffn_fused_kernel<<<grid, 256, smem_bytes>>>(x, pneff, w_in, out);
}